// round 6
// baseline (speedup 1.0000x reference)
#include <cuda_runtime.h>

// out[b] = sum_i cos(x[b,i]) * w[i] + bias ;  x: [1048576, 32] f32.
//
// One-shot warps, MLP=8: each warp issues 8 independent front-batched LDG.128
// (8 groups x 512B = 4KB contiguous), then consumes them in arrival order
// (compute of group k overlaps flight of groups k+1..7), reduces, stores, exits.
// Grid = 4096 blocks (~4+ waves) so the CTA scheduler keeps balancing.
//
// Lane l holds float4 #l of a 512B group (4 rows); chunk = l&7 selects the
// weight quad; 3-step shfl_xor within each 8-lane subgroup yields the 4 row sums.

__device__ __forceinline__ float group_dot(const float4& xv, const float4& wv)
{
    return __cosf(xv.x) * wv.x + __cosf(xv.y) * wv.y
         + __cosf(xv.z) * wv.z + __cosf(xv.w) * wv.w;
}

__device__ __forceinline__ float reduce8(float s)
{
    s += __shfl_xor_sync(0xffffffffu, s, 1);
    s += __shfl_xor_sync(0xffffffffu, s, 2);
    s += __shfl_xor_sync(0xffffffffu, s, 4);
    return s;
}

__global__ void __launch_bounds__(256) hybrid_regression_kernel(
    const float4* __restrict__ x4,
    const float*  __restrict__ w,
    const float*  __restrict__ bias,
    float*        __restrict__ out,
    int ngroups)
{
    int gtid  = blockIdx.x * blockDim.x + threadIdx.x;
    int warp  = gtid >> 5;
    int lane  = gtid & 31;
    int chunk = lane & 7;
    int sub   = lane >> 3;

    int g0 = warp * 8;                      // 8 groups per warp, one shot
    if (g0 >= ngroups) return;

    float4 wv = reinterpret_cast<const float4*>(w)[chunk];

    const float4* p = x4 + (size_t)g0 * 32 + lane;

    if (g0 + 8 <= ngroups) {
        // 8 independent coalesced 512B loads, front-batched (MLP=8)
        float4 xv0 = __ldcs(p +   0);
        float4 xv1 = __ldcs(p +  32);
        float4 xv2 = __ldcs(p +  64);
        float4 xv3 = __ldcs(p +  96);
        float4 xv4 = __ldcs(p + 128);
        float4 xv5 = __ldcs(p + 160);
        float4 xv6 = __ldcs(p + 192);
        float4 xv7 = __ldcs(p + 224);

        float bb = bias[0];

        // consume in arrival order: early groups' MUFU/SHFL overlaps late flight
        float s0 = reduce8(group_dot(xv0, wv));
        float s1 = reduce8(group_dot(xv1, wv));
        float s2 = reduce8(group_dot(xv2, wv));
        float s3 = reduce8(group_dot(xv3, wv));
        float s4 = reduce8(group_dot(xv4, wv));
        float s5 = reduce8(group_dot(xv5, wv));
        float s6 = reduce8(group_dot(xv6, wv));
        float s7 = reduce8(group_dot(xv7, wv));

        if (chunk == 0) {
            int r = g0 * 4 + sub;
            __stcs(out + r +  0, s0 + bb);
            __stcs(out + r +  4, s1 + bb);
            __stcs(out + r +  8, s2 + bb);
            __stcs(out + r + 12, s3 + bb);
            __stcs(out + r + 16, s4 + bb);
            __stcs(out + r + 20, s5 + bb);
            __stcs(out + r + 24, s6 + bb);
            __stcs(out + r + 28, s7 + bb);
        }
    } else {
        // tail (not hit for B=1048576, kept for generality)
        float bb = bias[0];
        for (int g = g0; g < ngroups; ++g) {
            float4 xv = __ldcs(x4 + (size_t)g * 32 + lane);
            float s = reduce8(group_dot(xv, wv));
            if (chunk == 0) out[g * 4 + sub] = s + bb;
        }
    }
}

extern "C" void kernel_launch(void* const* d_in, const int* in_sizes, int n_in,
                              void* d_out, int out_size)
{
    const float* x    = (const float*)d_in[0];   // [B, 32]
    // d_in[1] = theta: mathematically dead (RZ phase leaves <Z> unchanged)
    const float* w    = (const float*)d_in[2];   // [1, 32]
    const float* b    = (const float*)d_in[3];   // [1]
    float* out        = (float*)d_out;

    int batch   = in_sizes[0] / 32;
    int ngroups = batch / 4;                      // 262144

    int threads = 256;
    int warps_per_block   = threads / 32;         // 8
    int groups_per_block  = warps_per_block * 8;  // 64
    int blocks = (ngroups + groups_per_block - 1) / groups_per_block;  // 4096

    hybrid_regression_kernel<<<blocks, threads>>>(
        (const float4*)x, w, b, out, ngroups);
}